// round 2
// baseline (speedup 1.0000x reference)
#include <cuda_runtime.h>

#define NN 325
#define CNN (32*NN)
#define NT 352

static __device__ float g_X0[64*13*CNN];
static __device__ float g_X1[64*13*CNN];
static __device__ float g_skip[64*256*NN];

// ---- FMA-only exp2 (clamped to [-80,15]), err ~2e-6 -------------------------
__device__ __forceinline__ float fexp2(float x){
  x = fminf(fmaxf(x, -80.f), 15.f);
  float t = x + 12582912.f;              // round-to-nearest in mantissa
  int   bi = __float_as_int(t);
  float f  = x - (t - 12582912.f);       // f in [-0.5, 0.5]
  float p = fmaf(f, 1.3333558e-3f, 9.6181291e-3f);
  p = fmaf(f, p, 5.5504109e-2f);
  p = fmaf(f, p, 2.4022651e-1f);
  p = fmaf(f, p, 6.9314718e-1f);
  p = fmaf(f, p, 1.0f);
  return p * __int_as_float((bi - 0x4B3FFF81) << 23);   // * 2^round(x)
}
__device__ __forceinline__ float lg2_(float x){ float r; asm("lg2.approx.f32 %0,%1;":"=f"(r):"f"(x)); return r; }
__device__ __forceinline__ float rcp_(float x){ float r; asm("rcp.approx.f32 %0,%1;":"=f"(r):"f"(x)); return r; }

__device__ __forceinline__ float dot16(float4 a0,float4 a1,float4 a2,float4 a3,const float* p){
  float4 b0=((const float4*)p)[0],b1=((const float4*)p)[1],b2=((const float4*)p)[2],b3=((const float4*)p)[3];
  float s0=fmaf(a0.x,b0.x,fmaf(a0.y,b0.y,fmaf(a0.z,b0.z,a0.w*b0.w)));
  float s1=fmaf(a1.x,b1.x,fmaf(a1.y,b1.y,fmaf(a1.z,b1.z,a1.w*b1.w)));
  float s2=fmaf(a2.x,b2.x,fmaf(a2.y,b2.y,fmaf(a2.z,b2.z,a2.w*b2.w)));
  float s3=fmaf(a3.x,b3.x,fmaf(a3.y,b3.y,fmaf(a3.z,b3.z,a3.w*b3.w)));
  return (s0+s1)+(s2+s3);
}

// ---- start conv + skip zero -------------------------------------------------
__global__ __launch_bounds__(256) void start_kernel(const float* __restrict__ x,
                                                    const float* __restrict__ sW,
                                                    const float* __restrict__ sb){
  int i = blockIdx.x*256 + threadIdx.x;
  const int tot = 64*13*CNN;                 // 8,652,800
  if (i < tot){
    int n = i % NN; int r = i / NN;
    int c = r & 31; r >>= 5;
    int t = r % 13; int b = r / 13;
    float v0 = x[((b*2+0)*NN + n)*13 + t];
    float v1 = x[((b*2+1)*NN + n)*13 + t];
    g_X0[i] = fmaf(sW[c*2], v0, fmaf(sW[c*2+1], v1, sb[c]));
  } else {
    int j = i - tot;
    if (j < 64*256*NN) g_skip[j] = 0.f;
  }
}

// ---- fused layer kernel -----------------------------------------------------
// smem float offsets
#define OFF_GX   21248
#define OFF_W    33920
#define OFF_ROW  38080
#define LAYER_SMEM_BYTES (38432*4)

__global__ __launch_bounds__(NT,1) void layer_kernel(
    int layer, int dil, int parity, int do_att,
    const float* __restrict__ fW,  const float* __restrict__ fb,
    const float* __restrict__ gW,  const float* __restrict__ gb,
    const float* __restrict__ skW, const float* __restrict__ skb,
    const float* __restrict__ qW,  const float* __restrict__ qb,
    const float* __restrict__ kW,  const float* __restrict__ kb,
    const float* __restrict__ mW,  const float* __restrict__ mb,
    const float* __restrict__ bng, const float* __restrict__ bnb,
    const float* __restrict__ bnm, const float* __restrict__ bnv,
    const float* __restrict__ emb)
{
  extern __shared__ __align__(16) float sm[];
  const float* __restrict__ Xin  = parity ? g_X1 : g_X0;
  float* __restrict__       Xout = parity ? g_X0 : g_X1;
  const int t = blockIdx.x, b = blockIdx.y, tid = threadIdx.x;
  const int Tout = gridDim.x;

  float* s_xl  = sm;                 // [32][328]
  float* s_xr  = sm + 10496;         // [32][328]
  float* s_swt = sm;                 // [32][256] (skip phase, reuse)
  float* s_q   = sm;                 // [n][20]   (att phases, reuse)
  float* s_k   = sm + 6528;          // [n][20]
  float* s_gx  = sm + OFF_GX;        // [n][36]
  float* wreg  = sm + OFF_W;         // staged weights
  float* s_row = sm + OFF_ROW;       // [352]

  // stage gated weights interleaved [ci][co][f0,f1,g0,g1] + biases
  for (int idx = tid; idx < 4096; idx += NT){
    int ci = idx>>7, rem = idx&127, co = rem>>2, k = rem&3;
    wreg[idx] = (k<2) ? fW[((layer*32+co)*32+ci)*2 + k]
                      : gW[((layer*32+co)*32+ci)*2 + (k&1)];
  }
  if (tid < 64) wreg[4096+tid] = (tid<32) ? fb[layer*32+tid] : gb[layer*32+tid-32];
  const int base_in = (b*13 + t)*CNN;
  for (int idx = tid; idx < CNN; idx += NT){
    int ci = idx/NN, n2 = idx - ci*NN;
    s_xl[ci*328+n2] = Xin[base_in + idx];
    s_xr[ci*328+n2] = Xin[base_in + dil*CNN + idx];
  }
  __syncthreads();

  const int n = tid;

  // phase 1: gated dilated conv
  if (n < NN){
    float facc[32], gacc[32], vout[32];
    #pragma unroll
    for (int co=0; co<32; co++){ facc[co]=wreg[4096+co]; gacc[co]=wreg[4128+co]; }
    #pragma unroll 4
    for (int ci=0; ci<32; ci++){
      float xl = s_xl[ci*328+n], xr = s_xr[ci*328+n];
      const float4* wv = (const float4*)(wreg + ci*128);
      #pragma unroll
      for (int co=0; co<32; co++){
        float4 w = wv[co];
        facc[co] = fmaf(w.x, xl, fmaf(w.y, xr, facc[co]));
        gacc[co] = fmaf(w.z, xl, fmaf(w.w, xr, gacc[co]));
      }
    }
    #pragma unroll
    for (int co=0; co<32; co++){
      float ef = fexp2(-2.88539008f * facc[co]);   // e^{-2f}
      float eg = fexp2(-1.44269504f * gacc[co]);   // e^{-g}
      vout[co] = (1.f - ef) * rcp_((1.f + ef)*(1.f + eg));
    }
    float4* gp = (float4*)(s_gx + n*36);
    #pragma unroll
    for (int j=0;j<8;j++) gp[j] = ((float4*)vout)[j];
  }
  __syncthreads();

  // phase 1b: skip contribution (only last time index survives)
  if (t == Tout-1){
    for (int idx = tid; idx < 8192; idx += NT){
      int ci = idx>>8, o = idx&255;
      s_swt[idx] = skW[(layer*256+o)*32 + ci];
    }
    __syncthreads();
    if (n < NN){
      float* skp = g_skip + b*256*NN + n;
      #pragma unroll 1
      for (int ot=0; ot<8; ot++){
        float acc[32];
        #pragma unroll
        for (int j=0;j<32;j++) acc[j] = skb[layer*256 + ot*32 + j];
        #pragma unroll 4
        for (int ci=0; ci<32; ci++){
          float xv = s_gx[n*36+ci];
          const float4* wv = (const float4*)(s_swt + ci*256 + ot*32);
          #pragma unroll
          for (int j4=0;j4<8;j4++){
            float4 w = wv[j4];
            acc[4*j4+0]=fmaf(w.x,xv,acc[4*j4+0]); acc[4*j4+1]=fmaf(w.y,xv,acc[4*j4+1]);
            acc[4*j4+2]=fmaf(w.z,xv,acc[4*j4+2]); acc[4*j4+3]=fmaf(w.w,xv,acc[4*j4+3]);
          }
        }
        #pragma unroll
        for (int j=0;j<32;j++) skp[(ot*32+j)*NN] += acc[j];
      }
    }
  }
  __syncthreads();

  if (!do_att) return;

  // stage q/k interleaved, mlp^T, biases, bn
  for (int idx = tid; idx < 1536; idx += NT){
    int cin = idx>>5, r = idx&31, d = r>>1;
    wreg[idx] = ((r&1) ? kW : qW)[(layer*16+d)*48 + cin];
  }
  if (tid < 32) wreg[1536+tid] = ((tid&1) ? kb : qb)[layer*16 + (tid>>1)];
  for (int idx = tid; idx < 2048; idx += NT){
    int c = idx>>5, o = idx&31;
    wreg[1568+idx] = mW[(layer*32+o)*64 + c];
  }
  if (tid < 32){
    wreg[3616+tid] = mb[layer*32+tid];
    float sc = bng[layer*32+tid] * rsqrtf(bnv[layer*32+tid] + 1e-5f);
    wreg[3648+tid] = sc;
    wreg[3680+tid] = bnb[layer*32+tid] - bnm[layer*32+tid]*sc;
  }
  __syncthreads();

  // phase 2: q,k (fold 0.25*log2e into q)
  if (n < NN){
    float qa[16], ka[16];
    #pragma unroll
    for (int d=0; d<16; d++){ qa[d]=wreg[1536+2*d]; ka[d]=wreg[1537+2*d]; }
    #pragma unroll 4
    for (int ci=0; ci<32; ci++){
      float xv = s_gx[n*36+ci];
      const float2* wv = (const float2*)(wreg + ci*32);
      #pragma unroll
      for (int d=0; d<16; d++){ float2 w=wv[d]; qa[d]=fmaf(w.x,xv,qa[d]); ka[d]=fmaf(w.y,xv,ka[d]); }
    }
    #pragma unroll 4
    for (int e=0; e<16; e++){
      float xv = emb[e*NN+n];
      const float2* wv = (const float2*)(wreg + (32+e)*32);
      #pragma unroll
      for (int d=0; d<16; d++){ float2 w=wv[d]; qa[d]=fmaf(w.x,xv,qa[d]); ka[d]=fmaf(w.y,xv,ka[d]); }
    }
    #pragma unroll
    for (int d=0; d<16; d++){ s_q[n*20+d]=qa[d]*0.36067376f; s_k[n*20+d]=ka[d]; }
  }
  __syncthreads();

  // phase 3: row-softmax stats (two-pass, exp on FMA pipe)
  if (n < NN){
    const float4* qp = (const float4*)(s_q + n*20);
    float4 q0=qp[0],q1=qp[1],q2=qp[2],q3=qp[3];
    float mx = -1e30f;
    #pragma unroll 2
    for (int m=0; m<NN; m++) mx = fmaxf(mx, dot16(q0,q1,q2,q3, s_k + m*20));
    float Z = 0.f;
    #pragma unroll 2
    for (int m=0; m<NN; m++) Z += fexp2(dot16(q0,q1,q2,q3, s_k + m*20) - mx);
    s_row[n] = mx + lg2_(Z);
  }
  __syncthreads();

  // phase 4: column pass (xa) + mlp + residual + BN
  if (n < NN){
    const float4* kp = (const float4*)(s_k + n*20);
    float4 k0=kp[0],k1=kp[1],k2=kp[2],k3=kp[3];
    float xa[32];
    #pragma unroll
    for (int j=0;j<32;j++) xa[j]=0.f;
    for (int m=0; m<NN; m++){
      float s = dot16(k0,k1,k2,k3, s_q + m*20);
      float w = fexp2(s - s_row[m]);
      const float4* gv = (const float4*)(s_gx + m*36);
      #pragma unroll
      for (int j4=0;j4<8;j4++){
        float4 g4 = gv[j4];
        xa[4*j4+0]=fmaf(w,g4.x,xa[4*j4+0]); xa[4*j4+1]=fmaf(w,g4.y,xa[4*j4+1]);
        xa[4*j4+2]=fmaf(w,g4.z,xa[4*j4+2]); xa[4*j4+3]=fmaf(w,g4.w,xa[4*j4+3]);
      }
    }
    float o32[32];
    #pragma unroll
    for (int j=0;j<32;j++) o32[j] = wreg[3616+j];
    #pragma unroll 4
    for (int c=0; c<32; c++){
      float xv = s_gx[n*36+c];
      const float4* wv = (const float4*)(wreg + 1568 + c*32);
      #pragma unroll
      for (int j4=0;j4<8;j4++){
        float4 w = wv[j4];
        o32[4*j4+0]=fmaf(w.x,xv,o32[4*j4+0]); o32[4*j4+1]=fmaf(w.y,xv,o32[4*j4+1]);
        o32[4*j4+2]=fmaf(w.z,xv,o32[4*j4+2]); o32[4*j4+3]=fmaf(w.w,xv,o32[4*j4+3]);
      }
    }
    #pragma unroll 4
    for (int c=0; c<32; c++){
      float xv = xa[c];
      const float4* wv = (const float4*)(wreg + 1568 + (32+c)*32);
      #pragma unroll
      for (int j4=0;j4<8;j4++){
        float4 w = wv[j4];
        o32[4*j4+0]=fmaf(w.x,xv,o32[4*j4+0]); o32[4*j4+1]=fmaf(w.y,xv,o32[4*j4+1]);
        o32[4*j4+2]=fmaf(w.z,xv,o32[4*j4+2]); o32[4*j4+3]=fmaf(w.w,xv,o32[4*j4+3]);
      }
    }
    const float* rin = Xin + (b*13 + t + dil)*CNN + n;
    float* outp = Xout + (b*13 + t)*CNN + n;
    #pragma unroll
    for (int c=0; c<32; c++){
      float v = o32[c] + rin[c*NN];
      outp[c*NN] = fmaf(v, wreg[3648+c], wreg[3680+c]);
    }
  }
}

// ---- head: relu(skip) -> relu(512) -> 12 ------------------------------------
#define H_SS 0
#define H_W1 16384
#define H_H  32832
#define H_W2 37184
#define H_B1 43328
#define HEAD_SMEM_BYTES (43840*4)

__global__ __launch_bounds__(256,1) void head_kernel(
    const float* __restrict__ w1, const float* __restrict__ b1,
    const float* __restrict__ w2, const float* __restrict__ b2,
    float* __restrict__ out)
{
  extern __shared__ __align__(16) float sm[];
  float* s_s = sm + H_SS;   // [256][64]
  float* w1s = sm + H_W1;   // [64][257]
  float* h_s = sm + H_H;    // [64][68]
  float* w2t = sm + H_W2;   // [512][12]
  float* b1s = sm + H_B1;   // [512]
  const int tid = threadIdx.x;
  const int p0 = blockIdx.x*64;

  for (int idx = tid; idx < 16384; idx += 256){
    int c = idx>>6, j = idx&63, p = p0 + j;
    int b = p/NN, nn = p - b*NN;
    s_s[idx] = fmaxf(g_skip[(b*256+c)*NN + nn], 0.f);
  }
  for (int idx = tid; idx < 6144; idx += 256){
    int o = idx/12, oo = idx - o*12;
    w2t[idx] = w2[oo*512 + o];
  }
  for (int idx = tid; idx < 512; idx += 256) b1s[idx] = b1[idx];

  const int op  = tid & 63, jg = tid >> 6;       // compute role
  const int oo  = tid % 12, j0 = (tid/12)*4;     // fold role (tid<192)
  float accO[4] = {0.f,0.f,0.f,0.f};

  for (int ot = 0; ot < 8; ot++){
    __syncthreads();
    for (int idx = tid; idx < 16384; idx += 256){
      int o = idx>>8, c = idx&255;
      w1s[o*257+c] = w1[(ot*64+o)*256 + c];
    }
    __syncthreads();
    {
      float acc[16];
      float bv = b1s[ot*64+op];
      #pragma unroll
      for (int k=0;k<16;k++) acc[k]=bv;
      #pragma unroll 2
      for (int c=0; c<256; c++){
        float w = w1s[op*257+c];
        const float4* sp = (const float4*)(s_s + c*64 + jg*16);
        #pragma unroll
        for (int k4=0;k4<4;k4++){
          float4 s4 = sp[k4];
          acc[4*k4+0]=fmaf(w,s4.x,acc[4*k4+0]); acc[4*k4+1]=fmaf(w,s4.y,acc[4*k4+1]);
          acc[4*k4+2]=fmaf(w,s4.z,acc[4*k4+2]); acc[4*k4+3]=fmaf(w,s4.w,acc[4*k4+3]);
        }
      }
      float4* hp = (float4*)(h_s + op*68 + jg*16);
      #pragma unroll
      for (int k4=0;k4<4;k4++)
        hp[k4] = make_float4(fmaxf(acc[4*k4+0],0.f), fmaxf(acc[4*k4+1],0.f),
                             fmaxf(acc[4*k4+2],0.f), fmaxf(acc[4*k4+3],0.f));
    }
    __syncthreads();
    if (tid < 192){
      #pragma unroll 4
      for (int o=0; o<64; o++){
        float w = w2t[(ot*64+o)*12 + oo];
        const float4* hp = (const float4*)(h_s + o*68 + j0);
        float4 h4 = hp[0];
        accO[0]=fmaf(w,h4.x,accO[0]); accO[1]=fmaf(w,h4.y,accO[1]);
        accO[2]=fmaf(w,h4.z,accO[2]); accO[3]=fmaf(w,h4.w,accO[3]);
      }
    }
  }
  if (tid < 192){
    float bb = b2[oo];
    #pragma unroll
    for (int k=0;k<4;k++){
      int p = p0 + j0 + k;
      int b = p/NN, nn = p - b*NN;
      out[(b*12+oo)*NN + nn] = accO[k] + bb;
    }
  }
}

// ---- host -------------------------------------------------------------------
extern "C" void kernel_launch(void* const* d_in, const int* in_sizes, int n_in,
                              void* d_out, int out_size){
  const float* x    = (const float*)d_in[0];
  const float* emb  = (const float*)d_in[1];
  const float* stW  = (const float*)d_in[2];
  const float* stb  = (const float*)d_in[3];
  const float* fW   = (const float*)d_in[4];
  const float* fb   = (const float*)d_in[5];
  const float* gW   = (const float*)d_in[6];
  const float* gb   = (const float*)d_in[7];
  const float* skW  = (const float*)d_in[8];
  const float* skb  = (const float*)d_in[9];
  const float* qW   = (const float*)d_in[10];
  const float* qb   = (const float*)d_in[11];
  const float* kW   = (const float*)d_in[12];
  const float* kb   = (const float*)d_in[13];
  const float* mW   = (const float*)d_in[14];
  const float* mb   = (const float*)d_in[15];
  const float* bng  = (const float*)d_in[16];
  const float* bnb  = (const float*)d_in[17];
  const float* bnm  = (const float*)d_in[18];
  const float* bnv  = (const float*)d_in[19];
  const float* e1W  = (const float*)d_in[20];
  const float* e1b  = (const float*)d_in[21];
  const float* e2W  = (const float*)d_in[22];
  const float* e2b  = (const float*)d_in[23];
  float* out = (float*)d_out;

  cudaFuncSetAttribute(layer_kernel, cudaFuncAttributeMaxDynamicSharedMemorySize, LAYER_SMEM_BYTES);
  cudaFuncSetAttribute(head_kernel,  cudaFuncAttributeMaxDynamicSharedMemorySize, HEAD_SMEM_BYTES);

  start_kernel<<<54600, 256>>>(x, stW, stb);

  const int dil[8]  = {1,2,1,2,1,2,1,2};
  const int Tout[8] = {12,10,9,7,6,4,3,1};
  for (int i = 0; i < 8; i++){
    layer_kernel<<<dim3(Tout[i], 64), NT, LAYER_SMEM_BYTES>>>(
        i, dil[i], i & 1, (i != 7) ? 1 : 0,
        fW, fb, gW, gb, skW, skb, qW, qb, kW, kb, mW, mb,
        bng, bnb, bnm, bnv, emb);
  }

  head_kernel<<<325, 256, HEAD_SMEM_BYTES>>>(e1W, e1b, e2W, e2b, out);
}

// round 5
// speedup vs baseline: 1.0184x; 1.0184x over previous
#include <cuda_runtime.h>

#define NN 325
#define CNN (32*NN)
#define NT 704          // 2 threads per node slot (352 slots)

static __device__ float g_X0[64*13*CNN];
static __device__ float g_X1[64*13*CNN];
static __device__ float g_skip[64*256*NN];

// ---- FMA-only exp2, clamp [-126,15], err ~2e-6 ------------------------------
__device__ __forceinline__ float fexp2(float x){
  x = fminf(fmaxf(x, -126.f), 15.f);
  float t = x + 12582912.f;
  int   bi = __float_as_int(t);
  float f  = x - (t - 12582912.f);
  float p = fmaf(f, 1.3333558e-3f, 9.6181291e-3f);
  p = fmaf(f, p, 5.5504109e-2f);
  p = fmaf(f, p, 2.4022651e-1f);
  p = fmaf(f, p, 6.9314718e-1f);
  p = fmaf(f, p, 1.0f);
  return p * __int_as_float((bi - 0x4B3FFF81) << 23);
}
__device__ __forceinline__ float lg2_(float x){ float r; asm("lg2.approx.f32 %0,%1;":"=f"(r):"f"(x)); return r; }
__device__ __forceinline__ float rcp_(float x){ float r; asm("rcp.approx.f32 %0,%1;":"=f"(r):"f"(x)); return r; }

__device__ __forceinline__ float dot16(float4 a0,float4 a1,float4 a2,float4 a3,const float* p){
  float4 b0=((const float4*)p)[0],b1=((const float4*)p)[1],b2=((const float4*)p)[2],b3=((const float4*)p)[3];
  float s0=fmaf(a0.x,b0.x,fmaf(a0.y,b0.y,fmaf(a0.z,b0.z,a0.w*b0.w)));
  float s1=fmaf(a1.x,b1.x,fmaf(a1.y,b1.y,fmaf(a1.z,b1.z,a1.w*b1.w)));
  float s2=fmaf(a2.x,b2.x,fmaf(a2.y,b2.y,fmaf(a2.z,b2.z,a2.w*b2.w)));
  float s3=fmaf(a3.x,b3.x,fmaf(a3.y,b3.y,fmaf(a3.z,b3.z,a3.w*b3.w)));
  return (s0+s1)+(s2+s3);
}

// ---- start conv + skip zero -------------------------------------------------
__global__ __launch_bounds__(256) void start_kernel(const float* __restrict__ x,
                                                    const float* __restrict__ sW,
                                                    const float* __restrict__ sb){
  int i = blockIdx.x*256 + threadIdx.x;
  const int tot = 64*13*CNN;
  if (i < tot){
    int n = i % NN; int r = i / NN;
    int c = r & 31; r >>= 5;
    int t = r % 13; int b = r / 13;
    float v0 = x[((b*2+0)*NN + n)*13 + t];
    float v1 = x[((b*2+1)*NN + n)*13 + t];
    g_X0[i] = fmaf(sW[c*2], v0, fmaf(sW[c*2+1], v1, sb[c]));
  } else {
    int j = i - tot;
    if (j < 64*256*NN) g_skip[j] = 0.f;
  }
}

// ---- fused layer kernel -----------------------------------------------------
// smem float offsets (region 0..20992 is multi-use: xl/xr -> q/k/zp/mxp -> xa)
#define OFF_XR    10496
#define OFF_K     7040
#define OFF_ZP    14432    // [2][352] Z partials
#define OFF_MXP   15136    // [2][352] max partials
#define OFF_GX    20992    // [352][36]
#define OFF_SWT   33664    // [32][256]
#define OFF_W     41856    // staged weights (max 4160)
#define OFF_ROW   46048    // [352]
#define LAYER_SMEM_BYTES (46400*4)

__global__ __launch_bounds__(NT,1) void layer_kernel(
    int layer, int dil, int do_att, int parity,
    const float* __restrict__ fW,  const float* __restrict__ fb,
    const float* __restrict__ gW,  const float* __restrict__ gb,
    const float* __restrict__ skW, const float* __restrict__ skb,
    const float* __restrict__ qW,  const float* __restrict__ qb,
    const float* __restrict__ kW,  const float* __restrict__ kb,
    const float* __restrict__ mW,  const float* __restrict__ mb,
    const float* __restrict__ bng, const float* __restrict__ bnb,
    const float* __restrict__ bnm, const float* __restrict__ bnv,
    const float* __restrict__ emb)
{
  extern __shared__ __align__(16) float sm[];
  const float* __restrict__ Xin  = parity ? g_X1 : g_X0;
  float* __restrict__       Xout = parity ? g_X0 : g_X1;
  const int t = blockIdx.x, b = blockIdx.y, tid = threadIdx.x;
  const int Tout = gridDim.x;
  const int n = tid % 352;         // node slot (warp-aligned: 11 warps per half)
  const int h = tid / 352;         // work-half selector

  float* s_xl  = sm;               // [32][328] (phase 1)
  float* s_xr  = sm + OFF_XR;      // [32][328]
  float* s_q   = sm;               // [352][20] (phases 2-4)
  float* s_k   = sm + OFF_K;       // [352][20]
  float* s_zp  = sm + OFF_ZP;      // [2][352]
  float* s_mxp = sm + OFF_MXP;     // [2][352]
  float* s_xa  = sm;               // [352][33] (after xa loop)
  float* s_gx  = sm + OFF_GX;      // [352][36]
  float* s_swt = sm + OFF_SWT;     // [32][256]
  float* wreg  = sm + OFF_W;
  float* s_row = sm + OFF_ROW;

  // ---- stage gated weights [ci][co][f0,f1,g0,g1] + biases + input tiles -----
  for (int idx = tid; idx < 4096; idx += NT){
    int ci = idx>>7, rem = idx&127, co = rem>>2, k = rem&3;
    wreg[idx] = (k<2) ? fW[((layer*32+co)*32+ci)*2 + k]
                      : gW[((layer*32+co)*32+ci)*2 + (k&1)];
  }
  if (tid < 64) wreg[4096+tid] = (tid<32) ? fb[layer*32+tid] : gb[layer*32+tid-32];
  const int base_in = (b*13 + t)*CNN;
  for (int idx = tid; idx < CNN; idx += NT){
    int ci = idx/NN, n2 = idx - ci*NN;
    s_xl[ci*328+n2] = Xin[base_in + idx];
    s_xr[ci*328+n2] = Xin[base_in + dil*CNN + idx];
  }
  __syncthreads();

  // ---- phase 1: gated conv, half the output channels per thread -------------
  if (n < NN){
    float facc[16], gacc[16];
    #pragma unroll
    for (int co=0; co<16; co++){ facc[co]=wreg[4096+16*h+co]; gacc[co]=wreg[4128+16*h+co]; }
    #pragma unroll 4
    for (int ci=0; ci<32; ci++){
      float xl = s_xl[ci*328+n], xr = s_xr[ci*328+n];
      const float4* wv = (const float4*)(wreg + ci*128) + 16*h;
      #pragma unroll
      for (int co=0; co<16; co++){
        float4 w = wv[co];
        facc[co] = fmaf(w.x, xl, fmaf(w.y, xr, facc[co]));
        gacc[co] = fmaf(w.z, xl, fmaf(w.w, xr, gacc[co]));
      }
    }
    #pragma unroll
    for (int co=0; co<16; co++){
      float ef = fexp2(-2.88539008f * facc[co]);
      float eg = fexp2(-1.44269504f * gacc[co]);
      s_gx[n*36 + 16*h + co] = (1.f - ef) * rcp_((1.f + ef)*(1.f + eg));
    }
  }
  __syncthreads();

  // ---- stage attention-phase weights (and skip weights if last t) -----------
  if (do_att){
    for (int idx = tid; idx < 1536; idx += NT){          // wq [48][16] @0, wk [48][16] @768
      int half = (idx >= 768) ? 1 : 0;                   // FIXED split point
      int r = idx - half*768; int cin = r>>4, d = r&15;
      wreg[idx] = (half ? kW : qW)[(layer*16+d)*48 + cin];
    }
    if (tid < 32) wreg[1536+tid] = (tid<16) ? qb[layer*16+tid] : kb[layer*16+tid-16];
    for (int idx = tid; idx < 2048; idx += NT){          // mlp^T [64][32]
      int c = idx>>5, o = idx&31;
      wreg[1568+idx] = mW[(layer*32+o)*64 + c];
    }
    if (tid < 32){
      wreg[3616+tid] = mb[layer*32+tid];
      float sc = bng[layer*32+tid] * rsqrtf(bnv[layer*32+tid] + 1e-5f);
      wreg[3648+tid] = sc;
      wreg[3680+tid] = bnb[layer*32+tid] - bnm[layer*32+tid]*sc;
    }
  }
  if (t == Tout-1){
    for (int idx = tid; idx < 8192; idx += NT){
      int ci = idx>>8, o = idx&255;
      s_swt[idx] = skW[(layer*256+o)*32 + ci];           // [ci][o]
    }
  }
  __syncthreads();

  // ---- phase 1b: skip (only last time index survives), 4 ot-groups per half -
  if (t == Tout-1 && n < NN){
    float* skp = g_skip + b*256*NN + n;
    #pragma unroll 1
    for (int og=0; og<4; og++){
      int ot = 4*h + og;
      float acc[32];
      #pragma unroll
      for (int j=0;j<32;j++) acc[j] = skb[layer*256 + ot*32 + j];
      #pragma unroll 4
      for (int ci=0; ci<32; ci++){
        float xv = s_gx[n*36+ci];
        const float4* wv = (const float4*)(s_swt + ci*256 + ot*32);
        #pragma unroll
        for (int j4=0;j4<8;j4++){
          float4 w = wv[j4];
          acc[4*j4+0]=fmaf(w.x,xv,acc[4*j4+0]); acc[4*j4+1]=fmaf(w.y,xv,acc[4*j4+1]);
          acc[4*j4+2]=fmaf(w.z,xv,acc[4*j4+2]); acc[4*j4+3]=fmaf(w.w,xv,acc[4*j4+3]);
        }
      }
      #pragma unroll
      for (int j=0;j<32;j++) skp[(ot*32+j)*NN] += acc[j];
    }
  }
  if (!do_att) return;

  // ---- phase 2: h=0 computes q (log2e/4 folded), h=1 computes k -------------
  if (n < NN){
    const float QSC = 0.36067376f;   // log2e/4
    float a[16];
    const float* wb = wreg + 768*h;
    #pragma unroll
    for (int d=0; d<16; d++) a[d] = wreg[1536 + 16*h + d];
    #pragma unroll 4
    for (int ci=0; ci<32; ci++){
      float xv = s_gx[n*36+ci];
      const float4* wv = (const float4*)(wb + ci*16);
      #pragma unroll
      for (int d4=0; d4<4; d4++){
        float4 w = wv[d4];
        a[4*d4+0]=fmaf(w.x,xv,a[4*d4+0]); a[4*d4+1]=fmaf(w.y,xv,a[4*d4+1]);
        a[4*d4+2]=fmaf(w.z,xv,a[4*d4+2]); a[4*d4+3]=fmaf(w.w,xv,a[4*d4+3]);
      }
    }
    #pragma unroll 4
    for (int e=0; e<16; e++){
      float xv = emb[e*NN+n];
      const float4* wv = (const float4*)(wb + (32+e)*16);
      #pragma unroll
      for (int d4=0; d4<4; d4++){
        float4 w = wv[d4];
        a[4*d4+0]=fmaf(w.x,xv,a[4*d4+0]); a[4*d4+1]=fmaf(w.y,xv,a[4*d4+1]);
        a[4*d4+2]=fmaf(w.z,xv,a[4*d4+2]); a[4*d4+3]=fmaf(w.w,xv,a[4*d4+3]);
      }
    }
    if (h == 0){
      #pragma unroll
      for (int d=0; d<16; d++) s_q[n*20+d] = a[d]*QSC;
    } else {
      #pragma unroll
      for (int d=0; d<16; d++) s_k[n*20+d] = a[d];
    }
  }
  __syncthreads();

  const int m0 = h ? 163 : 0, m1 = h ? NN : 163;

  // ---- phase 3: split two-pass log-sum-exp (true max per half, then merge) --
  if (n < NN){
    const float4* qp = (const float4*)(s_q + n*20);
    float4 q0=qp[0],q1=qp[1],q2=qp[2],q3=qp[3];
    float mx = -1e30f;
    #pragma unroll 2
    for (int m=m0; m<m1; m++) mx = fmaxf(mx, dot16(q0,q1,q2,q3, s_k + m*20));
    float Z = 0.f;
    #pragma unroll 2
    for (int m=m0; m<m1; m++) Z += fexp2(dot16(q0,q1,q2,q3, s_k + m*20) - mx);
    s_mxp[h*352+n] = mx;
    s_zp [h*352+n] = Z;
  }
  __syncthreads();
  if (h == 0 && n < NN){
    float mx0 = s_mxp[n], mx1 = s_mxp[352+n];
    float mx  = fmaxf(mx0, mx1);
    float Z   = s_zp[n]*fexp2(mx0-mx) + s_zp[352+n]*fexp2(mx1-mx);
    s_row[n]  = mx + lg2_(Z);
  }
  __syncthreads();

  // ---- phase 4: column pass (xa) over m half-range --------------------------
  float xa[32];
  #pragma unroll
  for (int j=0;j<32;j++) xa[j]=0.f;
  if (n < NN){
    const float4* kp = (const float4*)(s_k + n*20);
    float4 k0=kp[0],k1=kp[1],k2=kp[2],k3=kp[3];
    for (int m=m0; m<m1; m++){
      float s = dot16(k0,k1,k2,k3, s_q + m*20);
      float w = fexp2(s - s_row[m]);
      const float4* gv = (const float4*)(s_gx + m*36);
      #pragma unroll
      for (int j4=0;j4<8;j4++){
        float4 g4 = gv[j4];
        xa[4*j4+0]=fmaf(w,g4.x,xa[4*j4+0]); xa[4*j4+1]=fmaf(w,g4.y,xa[4*j4+1]);
        xa[4*j4+2]=fmaf(w,g4.z,xa[4*j4+2]); xa[4*j4+3]=fmaf(w,g4.w,xa[4*j4+3]);
      }
    }
  }
  __syncthreads();                  // all xa dots done; s_q/s_k dead
  if (h == 0 && n < NN){
    #pragma unroll
    for (int j=0;j<32;j++) s_xa[n*33+j] = xa[j];
  }
  __syncthreads();
  if (h == 1 && n < NN){
    #pragma unroll
    for (int j=0;j<32;j++) s_xa[n*33+j] += xa[j];
  }
  __syncthreads();

  // ---- phase 5: mlp (16 outputs per thread) + residual + BN -----------------
  if (n < NN){
    float o16[16];
    #pragma unroll
    for (int j=0;j<16;j++) o16[j] = wreg[3616 + 16*h + j];
    #pragma unroll 4
    for (int c=0; c<32; c++){
      float xv = s_gx[n*36+c];
      const float4* wv = (const float4*)(wreg + 1568 + c*32 + 16*h);
      #pragma unroll
      for (int j4=0;j4<4;j4++){
        float4 w = wv[j4];
        o16[4*j4+0]=fmaf(w.x,xv,o16[4*j4+0]); o16[4*j4+1]=fmaf(w.y,xv,o16[4*j4+1]);
        o16[4*j4+2]=fmaf(w.z,xv,o16[4*j4+2]); o16[4*j4+3]=fmaf(w.w,xv,o16[4*j4+3]);
      }
    }
    #pragma unroll 4
    for (int c=0; c<32; c++){
      float xv = s_xa[n*33+c];
      const float4* wv = (const float4*)(wreg + 1568 + (32+c)*32 + 16*h);
      #pragma unroll
      for (int j4=0;j4<4;j4++){
        float4 w = wv[j4];
        o16[4*j4+0]=fmaf(w.x,xv,o16[4*j4+0]); o16[4*j4+1]=fmaf(w.y,xv,o16[4*j4+1]);
        o16[4*j4+2]=fmaf(w.z,xv,o16[4*j4+2]); o16[4*j4+3]=fmaf(w.w,xv,o16[4*j4+3]);
      }
    }
    const float* rin = Xin + (b*13 + t + dil)*CNN + n;
    float* outp = Xout + (b*13 + t)*CNN + n;
    #pragma unroll
    for (int j=0; j<16; j++){
      int c = 16*h + j;
      float v = o16[j] + rin[c*NN];
      outp[c*NN] = fmaf(v, wreg[3648+c], wreg[3680+c]);
    }
  }
}

// ---- head: relu(skip) -> relu(512) -> 12 ------------------------------------
#define H_SS 0
#define H_W1 16384
#define H_H  32832
#define H_W2 37184
#define H_B1 43328
#define HEAD_SMEM_BYTES (43840*4)

__global__ __launch_bounds__(256,1) void head_kernel(
    const float* __restrict__ w1, const float* __restrict__ b1,
    const float* __restrict__ w2, const float* __restrict__ b2,
    float* __restrict__ out)
{
  extern __shared__ __align__(16) float sm[];
  float* s_s = sm + H_SS;   // [256][64]
  float* w1s = sm + H_W1;   // [64][257]
  float* h_s = sm + H_H;    // [64][68]
  float* w2t = sm + H_W2;   // [512][12]
  float* b1s = sm + H_B1;   // [512]
  const int tid = threadIdx.x;
  const int p0 = blockIdx.x*64;

  for (int idx = tid; idx < 16384; idx += 256){
    int c = idx>>6, j = idx&63, p = p0 + j;
    int b = p/NN, nn = p - b*NN;
    s_s[idx] = fmaxf(g_skip[(b*256+c)*NN + nn], 0.f);
  }
  for (int idx = tid; idx < 6144; idx += 256){
    int o = idx/12, oo = idx - o*12;
    w2t[idx] = w2[oo*512 + o];
  }
  for (int idx = tid; idx < 512; idx += 256) b1s[idx] = b1[idx];

  const int op  = tid & 63, jg = tid >> 6;
  const int oo  = tid % 12, j0 = (tid/12)*4;
  float accO[4] = {0.f,0.f,0.f,0.f};

  for (int ot = 0; ot < 8; ot++){
    __syncthreads();
    for (int idx = tid; idx < 16384; idx += 256){
      int o = idx>>8, c = idx&255;
      w1s[o*257+c] = w1[(ot*64+o)*256 + c];
    }
    __syncthreads();
    {
      float acc[16];
      float bv = b1s[ot*64+op];
      #pragma unroll
      for (int k=0;k<16;k++) acc[k]=bv;
      #pragma unroll 2
      for (int c=0; c<256; c++){
        float w = w1s[op*257+c];
        const float4* sp = (const float4*)(s_s + c*64 + jg*16);
        #pragma unroll
        for (int k4=0;k4<4;k4++){
          float4 s4 = sp[k4];
          acc[4*k4+0]=fmaf(w,s4.x,acc[4*k4+0]); acc[4*k4+1]=fmaf(w,s4.y,acc[4*k4+1]);
          acc[4*k4+2]=fmaf(w,s4.z,acc[4*k4+2]); acc[4*k4+3]=fmaf(w,s4.w,acc[4*k4+3]);
        }
      }
      float4* hp = (float4*)(h_s + op*68 + jg*16);
      #pragma unroll
      for (int k4=0;k4<4;k4++)
        hp[k4] = make_float4(fmaxf(acc[4*k4+0],0.f), fmaxf(acc[4*k4+1],0.f),
                             fmaxf(acc[4*k4+2],0.f), fmaxf(acc[4*k4+3],0.f));
    }
    __syncthreads();
    if (tid < 192){
      #pragma unroll 4
      for (int o=0; o<64; o++){
        float w = w2t[(ot*64+o)*12 + oo];
        const float4* hp = (const float4*)(h_s + o*68 + j0);
        float4 h4 = hp[0];
        accO[0]=fmaf(w,h4.x,accO[0]); accO[1]=fmaf(w,h4.y,accO[1]);
        accO[2]=fmaf(w,h4.z,accO[2]); accO[3]=fmaf(w,h4.w,accO[3]);
      }
    }
  }
  if (tid < 192){
    float bb = b2[oo];
    #pragma unroll
    for (int k=0;k<4;k++){
      int p = p0 + j0 + k;
      int b = p/NN, nn = p - b*NN;
      out[(b*12+oo)*NN + nn] = accO[k] + bb;
    }
  }
}

// ---- host -------------------------------------------------------------------
extern "C" void kernel_launch(void* const* d_in, const int* in_sizes, int n_in,
                              void* d_out, int out_size){
  const float* x    = (const float*)d_in[0];
  const float* emb  = (const float*)d_in[1];
  const float* stW  = (const float*)d_in[2];
  const float* stb  = (const float*)d_in[3];
  const float* fW   = (const float*)d_in[4];
  const float* fb   = (const float*)d_in[5];
  const float* gW   = (const float*)d_in[6];
  const float* gb   = (const float*)d_in[7];
  const float* skW  = (const float*)d_in[8];
  const float* skb  = (const float*)d_in[9];
  const float* qW   = (const float*)d_in[10];
  const float* qb   = (const float*)d_in[11];
  const float* kW   = (const float*)d_in[12];
  const float* kb   = (const float*)d_in[13];
  const float* mW   = (const float*)d_in[14];
  const float* mb   = (const float*)d_in[15];
  const float* bng  = (const float*)d_in[16];
  const float* bnb  = (const float*)d_in[17];
  const float* bnm  = (const float*)d_in[18];
  const float* bnv  = (const float*)d_in[19];
  const float* e1W  = (const float*)d_in[20];
  const float* e1b  = (const float*)d_in[21];
  const float* e2W  = (const float*)d_in[22];
  const float* e2b  = (const float*)d_in[23];
  float* out = (float*)d_out;

  cudaFuncSetAttribute(layer_kernel, cudaFuncAttributeMaxDynamicSharedMemorySize, LAYER_SMEM_BYTES);
  cudaFuncSetAttribute(head_kernel,  cudaFuncAttributeMaxDynamicSharedMemorySize, HEAD_SMEM_BYTES);

  start_kernel<<<54600, 256>>>(x, stW, stb);

  const int dil[8]  = {1,2,1,2,1,2,1,2};
  const int Tout[8] = {12,10,9,7,6,4,3,1};
  for (int i = 0; i < 8; i++){
    layer_kernel<<<dim3(Tout[i], 64), NT, LAYER_SMEM_BYTES>>>(
        i, dil[i], (i != 7) ? 1 : 0, i & 1,
        fW, fb, gW, gb, skW, skb, qW, qb, kW, kb, mW, mb,
        bng, bnb, bnm, bnv, emb);
  }

  head_kernel<<<325, 256, HEAD_SMEM_BYTES>>>(e1W, e1b, e2W, e2b, out);
}

// round 6
// speedup vs baseline: 1.1987x; 1.1771x over previous
#include <cuda_runtime.h>

#define NN 325
#define CNN (32*NN)
#define NT 704          // 2 threads per node slot (352 slots)

static __device__ float g_X0[64*13*CNN];
static __device__ float g_X1[64*13*CNN];
static __device__ float g_skip[64*256*NN];

// ---- MUFU helpers (SFU pipe; rel err ~1e-6) ---------------------------------
__device__ __forceinline__ float ex2_(float x){ float r; asm("ex2.approx.f32 %0,%1;":"=f"(r):"f"(x)); return r; }
__device__ __forceinline__ float lg2_(float x){ float r; asm("lg2.approx.f32 %0,%1;":"=f"(r):"f"(x)); return r; }
__device__ __forceinline__ float rcp_(float x){ float r; asm("rcp.approx.f32 %0,%1;":"=f"(r):"f"(x)); return r; }

__device__ __forceinline__ float dot16(float4 a0,float4 a1,float4 a2,float4 a3,const float* p){
  float4 b0=((const float4*)p)[0],b1=((const float4*)p)[1],b2=((const float4*)p)[2],b3=((const float4*)p)[3];
  float s0=fmaf(a0.x,b0.x,fmaf(a0.y,b0.y,fmaf(a0.z,b0.z,a0.w*b0.w)));
  float s1=fmaf(a1.x,b1.x,fmaf(a1.y,b1.y,fmaf(a1.z,b1.z,a1.w*b1.w)));
  float s2=fmaf(a2.x,b2.x,fmaf(a2.y,b2.y,fmaf(a2.z,b2.z,a2.w*b2.w)));
  float s3=fmaf(a3.x,b3.x,fmaf(a3.y,b3.y,fmaf(a3.z,b3.z,a3.w*b3.w)));
  return (s0+s1)+(s2+s3);
}

// ---- start conv + skip zero -------------------------------------------------
__global__ __launch_bounds__(256) void start_kernel(const float* __restrict__ x,
                                                    const float* __restrict__ sW,
                                                    const float* __restrict__ sb){
  int i = blockIdx.x*256 + threadIdx.x;
  const int tot = 64*13*CNN;
  if (i < tot){
    int n = i % NN; int r = i / NN;
    int c = r & 31; r >>= 5;
    int t = r % 13; int b = r / 13;
    float v0 = x[((b*2+0)*NN + n)*13 + t];
    float v1 = x[((b*2+1)*NN + n)*13 + t];
    g_X0[i] = fmaf(sW[c*2], v0, fmaf(sW[c*2+1], v1, sb[c]));
  } else {
    int j = i - tot;
    if (j < 64*256*NN) g_skip[j] = 0.f;
  }
}

// ---- fused layer kernel -----------------------------------------------------
// scratch region (multi-use): swt[32][256] -> q[352][20],k[352][20],mxp,zp -> xa[352][36]
#define OFF_K     7040
#define OFF_MXP   14080
#define OFF_ZP    14784
#define OFF_GX    15488    // [352][36]
#define OFF_W     28160    // staged weights (max 4192)
#define OFF_ROW   32352    // [352]
#define LAYER_SMEM_BYTES (32704*4)

__global__ __launch_bounds__(NT,1) void layer_kernel(
    int layer, int dil, int do_att, int parity,
    const float* __restrict__ fW,  const float* __restrict__ fb,
    const float* __restrict__ gW,  const float* __restrict__ gb,
    const float* __restrict__ skW, const float* __restrict__ skb,
    const float* __restrict__ qW,  const float* __restrict__ qb,
    const float* __restrict__ kW,  const float* __restrict__ kb,
    const float* __restrict__ mW,  const float* __restrict__ mb,
    const float* __restrict__ bng, const float* __restrict__ bnb,
    const float* __restrict__ bnm, const float* __restrict__ bnv,
    const float* __restrict__ emb)
{
  extern __shared__ __align__(16) float sm[];
  const float* __restrict__ Xin  = parity ? g_X1 : g_X0;
  float* __restrict__       Xout = parity ? g_X0 : g_X1;
  const int t = blockIdx.x, b = blockIdx.y, tid = threadIdx.x;
  const int Tout = gridDim.x;
  const int n = tid % 352;         // node slot (warp-aligned: 11 warps per half)
  const int h = tid / 352;         // work-half selector
  const int last_t = (t == Tout-1);

  float* s_swt = sm;               // [32][256] (phase 0..1b)
  float* s_q   = sm;               // [352][20] (phases 2-4)
  float* s_k   = sm + OFF_K;       // [352][20]
  float* s_mxp = sm + OFF_MXP;     // [2][352]
  float* s_zp  = sm + OFF_ZP;      // [2][352]
  float* s_xa  = sm;               // [352][36] (after xa loop)
  float* s_gx  = sm + OFF_GX;      // [352][36]
  float* wreg  = sm + OFF_W;
  float* s_row = sm + OFF_ROW;

  // ---- phase 0: stage gated weights [ci][co][f0,f1,g0,g1] + biases (+ skipW)
  for (int idx = tid; idx < 4096; idx += NT){
    int ci = idx>>7, rem = idx&127, co = rem>>2, k = rem&3;
    wreg[idx] = (k<2) ? fW[((layer*32+co)*32+ci)*2 + k]
                      : gW[((layer*32+co)*32+ci)*2 + (k&1)];
  }
  if (tid < 64) wreg[4096+tid] = (tid<32) ? fb[layer*32+tid] : gb[layer*32+tid-32];
  if (last_t){
    for (int idx = tid; idx < 8192; idx += NT){
      int ci = idx>>8, o = idx&255;
      s_swt[idx] = skW[(layer*256+o)*32 + ci];           // transposed [ci][o]
    }
  }
  __syncthreads();

  // ---- phase 1: gated conv, direct global reads (L2-resident), half channels
  const int base_in = (b*13 + t)*CNN;
  if (n < NN){
    const float* xin = Xin + base_in + n;
    const float* xrn = xin + dil*CNN;
    float facc[16], gacc[16];
    #pragma unroll
    for (int co=0; co<16; co++){ facc[co]=wreg[4096+16*h+co]; gacc[co]=wreg[4128+16*h+co]; }
    #pragma unroll 4
    for (int ci=0; ci<32; ci++){
      float xl = xin[ci*NN], xr = xrn[ci*NN];
      const float4* wv = (const float4*)(wreg + ci*128) + 16*h;
      #pragma unroll
      for (int co=0; co<16; co++){
        float4 w = wv[co];
        facc[co] = fmaf(w.x, xl, fmaf(w.y, xr, facc[co]));
        gacc[co] = fmaf(w.z, xl, fmaf(w.w, xr, gacc[co]));
      }
    }
    #pragma unroll
    for (int co=0; co<16; co++){
      float ef = ex2_(-2.88539008f * facc[co]);          // e^{-2f}
      float eg = ex2_(-1.44269504f * gacc[co]);          // e^{-g}
      s_gx[n*36 + 16*h + co] = (1.f - ef) * rcp_((1.f + ef)*(1.f + eg));
    }
  }
  __syncthreads();

  // ---- stage attention-phase weights ----------------------------------------
  if (do_att){
    for (int idx = tid; idx < 1536; idx += NT){          // wq [48][16] @0, wk @768
      int half = (idx >= 768) ? 1 : 0;
      int r = idx - half*768; int cin = r>>4, d = r&15;
      wreg[idx] = (half ? kW : qW)[(layer*16+d)*48 + cin];
    }
    if (tid < 32) wreg[1536+tid] = (tid<16) ? qb[layer*16+tid] : kb[layer*16+tid-16];
    for (int idx = tid; idx < 2048; idx += NT){          // mlp^T [64][32]
      int c = idx>>5, o = idx&31;
      wreg[1568+idx] = mW[(layer*32+o)*64 + c];
    }
    if (tid < 32){
      wreg[3616+tid] = mb[layer*32+tid];
      float sc = bng[layer*32+tid] * rsqrtf(bnv[layer*32+tid] + 1e-5f);
      wreg[3648+tid] = sc;
      wreg[3680+tid] = bnb[layer*32+tid] - bnm[layer*32+tid]*sc;
    }
  }

  // ---- phase 1b: skip contribution (only last time index survives) ----------
  if (last_t && n < NN){
    float* skp = g_skip + b*256*NN + n;
    const float4* gxv = (const float4*)(s_gx + n*36);
    #pragma unroll 1
    for (int og=0; og<4; og++){
      int ot = 4*h + og;
      float acc[32];
      #pragma unroll
      for (int j=0;j<32;j++) acc[j] = skb[layer*256 + ot*32 + j];
      #pragma unroll 2
      for (int ci4=0; ci4<8; ci4++){
        float4 g4 = gxv[ci4];
        #pragma unroll
        for (int jj=0; jj<4; jj++){
          float xv = (jj==0)?g4.x:(jj==1)?g4.y:(jj==2)?g4.z:g4.w;
          const float4* wv = (const float4*)(s_swt + (ci4*4+jj)*256 + ot*32);
          #pragma unroll
          for (int j4=0;j4<8;j4++){
            float4 w = wv[j4];
            acc[4*j4+0]=fmaf(w.x,xv,acc[4*j4+0]); acc[4*j4+1]=fmaf(w.y,xv,acc[4*j4+1]);
            acc[4*j4+2]=fmaf(w.z,xv,acc[4*j4+2]); acc[4*j4+3]=fmaf(w.w,xv,acc[4*j4+3]);
          }
        }
      }
      #pragma unroll
      for (int j=0;j<32;j++) skp[(ot*32+j)*NN] += acc[j];
    }
  }
  if (!do_att) return;
  __syncthreads();    // skip/swt reads done; wreg staged; scratch free for q/k

  // ---- phase 2: h=0 computes q (log2e/4 folded), h=1 computes k -------------
  if (n < NN){
    const float QSC = 0.36067376f;   // log2e/4
    float a[16];
    const float* wb = wreg + 768*h;
    #pragma unroll
    for (int d=0; d<16; d++) a[d] = wreg[1536 + 16*h + d];
    const float4* gxv = (const float4*)(s_gx + n*36);
    #pragma unroll 2
    for (int ci4=0; ci4<8; ci4++){
      float4 g4 = gxv[ci4];
      #pragma unroll
      for (int jj=0; jj<4; jj++){
        float xv = (jj==0)?g4.x:(jj==1)?g4.y:(jj==2)?g4.z:g4.w;
        const float4* wv = (const float4*)(wb + (ci4*4+jj)*16);
        #pragma unroll
        for (int d4=0; d4<4; d4++){
          float4 w = wv[d4];
          a[4*d4+0]=fmaf(w.x,xv,a[4*d4+0]); a[4*d4+1]=fmaf(w.y,xv,a[4*d4+1]);
          a[4*d4+2]=fmaf(w.z,xv,a[4*d4+2]); a[4*d4+3]=fmaf(w.w,xv,a[4*d4+3]);
        }
      }
    }
    #pragma unroll 4
    for (int e=0; e<16; e++){
      float xv = emb[e*NN+n];
      const float4* wv = (const float4*)(wb + (32+e)*16);
      #pragma unroll
      for (int d4=0; d4<4; d4++){
        float4 w = wv[d4];
        a[4*d4+0]=fmaf(w.x,xv,a[4*d4+0]); a[4*d4+1]=fmaf(w.y,xv,a[4*d4+1]);
        a[4*d4+2]=fmaf(w.z,xv,a[4*d4+2]); a[4*d4+3]=fmaf(w.w,xv,a[4*d4+3]);
      }
    }
    if (h == 0){
      #pragma unroll
      for (int d=0; d<16; d++) s_q[n*20+d] = a[d]*QSC;
    } else {
      #pragma unroll
      for (int d=0; d<16; d++) s_k[n*20+d] = a[d];
    }
  }
  __syncthreads();

  const int m0 = h ? 163 : 0, m1 = h ? NN : 163;

  // ---- phase 3: online single-pass log-sum-exp over m half-range ------------
  if (n < NN){
    const float4* qp = (const float4*)(s_q + n*20);
    float4 q0=qp[0],q1=qp[1],q2=qp[2],q3=qp[3];
    float mx = -1e30f, Z = 0.f;
    #pragma unroll 2
    for (int m=m0; m<m1; m++){
      float s = dot16(q0,q1,q2,q3, s_k + m*20);
      float nm = fmaxf(mx, s);
      Z = fmaf(Z, ex2_(mx - nm), ex2_(s - nm));
      mx = nm;
    }
    s_mxp[h*352+n] = mx;
    s_zp [h*352+n] = Z;
  }
  __syncthreads();
  if (h == 0 && n < NN){
    float mx0 = s_mxp[n], mx1 = s_mxp[352+n];
    float mx  = fmaxf(mx0, mx1);
    float Z   = s_zp[n]*ex2_(mx0-mx) + s_zp[352+n]*ex2_(mx1-mx);
    s_row[n]  = mx + lg2_(Z);
  }
  __syncthreads();

  // ---- phase 4: column pass (xa) over m half-range --------------------------
  float xa[32];
  #pragma unroll
  for (int j=0;j<32;j++) xa[j]=0.f;
  if (n < NN){
    const float4* kp = (const float4*)(s_k + n*20);
    float4 k0=kp[0],k1=kp[1],k2=kp[2],k3=kp[3];
    #pragma unroll 2
    for (int m=m0; m<m1; m++){
      float s = dot16(k0,k1,k2,k3, s_q + m*20);
      float w = ex2_(s - s_row[m]);
      const float4* gv = (const float4*)(s_gx + m*36);
      #pragma unroll
      for (int j4=0;j4<8;j4++){
        float4 g4 = gv[j4];
        xa[4*j4+0]=fmaf(w,g4.x,xa[4*j4+0]); xa[4*j4+1]=fmaf(w,g4.y,xa[4*j4+1]);
        xa[4*j4+2]=fmaf(w,g4.z,xa[4*j4+2]); xa[4*j4+3]=fmaf(w,g4.w,xa[4*j4+3]);
      }
    }
  }
  __syncthreads();                  // all xa dots done; s_q/s_k dead
  if (h == 0 && n < NN){
    float4* xp = (float4*)(s_xa + n*36);
    #pragma unroll
    for (int j4=0;j4<8;j4++) xp[j4] = make_float4(xa[4*j4],xa[4*j4+1],xa[4*j4+2],xa[4*j4+3]);
  }
  __syncthreads();
  if (h == 1 && n < NN){
    float4* xp = (float4*)(s_xa + n*36);
    #pragma unroll
    for (int j4=0;j4<8;j4++){
      float4 v = xp[j4];
      xp[j4] = make_float4(v.x+xa[4*j4], v.y+xa[4*j4+1], v.z+xa[4*j4+2], v.w+xa[4*j4+3]);
    }
  }
  __syncthreads();

  // ---- phase 5: mlp (16 outputs per thread) + residual + BN -----------------
  if (n < NN){
    float o16[16];
    #pragma unroll
    for (int j=0;j<16;j++) o16[j] = wreg[3616 + 16*h + j];
    const float4* gxv = (const float4*)(s_gx + n*36);
    const float4* xav = (const float4*)(s_xa + n*36);
    #pragma unroll 2
    for (int ci4=0; ci4<8; ci4++){
      float4 g4 = gxv[ci4];
      #pragma unroll
      for (int jj=0; jj<4; jj++){
        float xv = (jj==0)?g4.x:(jj==1)?g4.y:(jj==2)?g4.z:g4.w;
        const float4* wv = (const float4*)(wreg + 1568 + (ci4*4+jj)*32 + 16*h);
        #pragma unroll
        for (int j4=0;j4<4;j4++){
          float4 w = wv[j4];
          o16[4*j4+0]=fmaf(w.x,xv,o16[4*j4+0]); o16[4*j4+1]=fmaf(w.y,xv,o16[4*j4+1]);
          o16[4*j4+2]=fmaf(w.z,xv,o16[4*j4+2]); o16[4*j4+3]=fmaf(w.w,xv,o16[4*j4+3]);
        }
      }
    }
    #pragma unroll 2
    for (int ci4=0; ci4<8; ci4++){
      float4 g4 = xav[ci4];
      #pragma unroll
      for (int jj=0; jj<4; jj++){
        float xv = (jj==0)?g4.x:(jj==1)?g4.y:(jj==2)?g4.z:g4.w;
        const float4* wv = (const float4*)(wreg + 1568 + (32+ci4*4+jj)*32 + 16*h);
        #pragma unroll
        for (int j4=0;j4<4;j4++){
          float4 w = wv[j4];
          o16[4*j4+0]=fmaf(w.x,xv,o16[4*j4+0]); o16[4*j4+1]=fmaf(w.y,xv,o16[4*j4+1]);
          o16[4*j4+2]=fmaf(w.z,xv,o16[4*j4+2]); o16[4*j4+3]=fmaf(w.w,xv,o16[4*j4+3]);
        }
      }
    }
    const float* rin = Xin + base_in + dil*CNN + n;
    float* outp = Xout + base_in + n;
    #pragma unroll
    for (int j=0; j<16; j++){
      int c = 16*h + j;
      float v = o16[j] + rin[c*NN];
      outp[c*NN] = fmaf(v, wreg[3648+c], wreg[3680+c]);
    }
  }
}

// ---- head: relu(skip) -> relu(512) -> 12 ------------------------------------
#define H_SS 0
#define H_W1 16384
#define H_H  32832
#define H_W2 37184
#define H_B1 43328
#define HEAD_SMEM_BYTES (43840*4)

__global__ __launch_bounds__(256,1) void head_kernel(
    const float* __restrict__ w1, const float* __restrict__ b1,
    const float* __restrict__ w2, const float* __restrict__ b2,
    float* __restrict__ out)
{
  extern __shared__ __align__(16) float sm[];
  float* s_s = sm + H_SS;   // [256][64]
  float* w1s = sm + H_W1;   // [64][257]
  float* h_s = sm + H_H;    // [64][68]
  float* w2t = sm + H_W2;   // [512][12]
  float* b1s = sm + H_B1;   // [512]
  const int tid = threadIdx.x;
  const int p0 = blockIdx.x*64;

  for (int idx = tid; idx < 16384; idx += 256){
    int c = idx>>6, j = idx&63, p = p0 + j;
    int b = p/NN, nn = p - b*NN;
    s_s[idx] = fmaxf(g_skip[(b*256+c)*NN + nn], 0.f);
  }
  for (int idx = tid; idx < 6144; idx += 256){
    int o = idx/12, oo = idx - o*12;
    w2t[idx] = w2[oo*512 + o];
  }
  for (int idx = tid; idx < 512; idx += 256) b1s[idx] = b1[idx];

  const int op  = tid & 63, jg = tid >> 6;
  const int oo  = tid % 12, j0 = (tid/12)*4;
  float accO[4] = {0.f,0.f,0.f,0.f};

  for (int ot = 0; ot < 8; ot++){
    __syncthreads();
    for (int idx = tid; idx < 16384; idx += 256){
      int o = idx>>8, c = idx&255;
      w1s[o*257+c] = w1[(ot*64+o)*256 + c];
    }
    __syncthreads();
    {
      float acc[16];
      float bv = b1s[ot*64+op];
      #pragma unroll
      for (int k=0;k<16;k++) acc[k]=bv;
      #pragma unroll 2
      for (int c=0; c<256; c++){
        float w = w1s[op*257+c];
        const float4* sp = (const float4*)(s_s + c*64 + jg*16);
        #pragma unroll
        for (int k4=0;k4<4;k4++){
          float4 s4 = sp[k4];
          acc[4*k4+0]=fmaf(w,s4.x,acc[4*k4+0]); acc[4*k4+1]=fmaf(w,s4.y,acc[4*k4+1]);
          acc[4*k4+2]=fmaf(w,s4.z,acc[4*k4+2]); acc[4*k4+3]=fmaf(w,s4.w,acc[4*k4+3]);
        }
      }
      float4* hp = (float4*)(h_s + op*68 + jg*16);
      #pragma unroll
      for (int k4=0;k4<4;k4++)
        hp[k4] = make_float4(fmaxf(acc[4*k4+0],0.f), fmaxf(acc[4*k4+1],0.f),
                             fmaxf(acc[4*k4+2],0.f), fmaxf(acc[4*k4+3],0.f));
    }
    __syncthreads();
    if (tid < 192){
      #pragma unroll 4
      for (int o=0; o<64; o++){
        float w = w2t[(ot*64+o)*12 + oo];
        const float4* hp = (const float4*)(h_s + o*68 + j0);
        float4 h4 = hp[0];
        accO[0]=fmaf(w,h4.x,accO[0]); accO[1]=fmaf(w,h4.y,accO[1]);
        accO[2]=fmaf(w,h4.z,accO[2]); accO[3]=fmaf(w,h4.w,accO[3]);
      }
    }
  }
  if (tid < 192){
    float bb = b2[oo];
    #pragma unroll
    for (int k=0;k<4;k++){
      int p = p0 + j0 + k;
      int b = p/NN, nn = p - b*NN;
      out[(b*12+oo)*NN + nn] = accO[k] + bb;
    }
  }
}

// ---- host -------------------------------------------------------------------
extern "C" void kernel_launch(void* const* d_in, const int* in_sizes, int n_in,
                              void* d_out, int out_size){
  const float* x    = (const float*)d_in[0];
  const float* emb  = (const float*)d_in[1];
  const float* stW  = (const float*)d_in[2];
  const float* stb  = (const float*)d_in[3];
  const float* fW   = (const float*)d_in[4];
  const float* fb   = (const float*)d_in[5];
  const float* gW   = (const float*)d_in[6];
  const float* gb   = (const float*)d_in[7];
  const float* skW  = (const float*)d_in[8];
  const float* skb  = (const float*)d_in[9];
  const float* qW   = (const float*)d_in[10];
  const float* qb   = (const float*)d_in[11];
  const float* kW   = (const float*)d_in[12];
  const float* kb   = (const float*)d_in[13];
  const float* mW   = (const float*)d_in[14];
  const float* mb   = (const float*)d_in[15];
  const float* bng  = (const float*)d_in[16];
  const float* bnb  = (const float*)d_in[17];
  const float* bnm  = (const float*)d_in[18];
  const float* bnv  = (const float*)d_in[19];
  const float* e1W  = (const float*)d_in[20];
  const float* e1b  = (const float*)d_in[21];
  const float* e2W  = (const float*)d_in[22];
  const float* e2b  = (const float*)d_in[23];
  float* out = (float*)d_out;

  cudaFuncSetAttribute(layer_kernel, cudaFuncAttributeMaxDynamicSharedMemorySize, LAYER_SMEM_BYTES);
  cudaFuncSetAttribute(head_kernel,  cudaFuncAttributeMaxDynamicSharedMemorySize, HEAD_SMEM_BYTES);

  start_kernel<<<54600, 256>>>(x, stW, stb);

  const int dil[8]  = {1,2,1,2,1,2,1,2};
  const int Tout[8] = {12,10,9,7,6,4,3,1};
  for (int i = 0; i < 8; i++){
    layer_kernel<<<dim3(Tout[i], 64), NT, LAYER_SMEM_BYTES>>>(
        i, dil[i], (i != 7) ? 1 : 0, i & 1,
        fW, fb, gW, gb, skW, skb, qW, qb, kW, kb, mW, mb,
        bng, bnb, bnm, bnv, emb);
  }

  head_kernel<<<325, 256, HEAD_SMEM_BYTES>>>(e1W, e1b, e2W, e2b, out);
}

// round 7
// speedup vs baseline: 1.2794x; 1.0673x over previous
#include <cuda_runtime.h>

#define NN 325
#define CNN (32*NN)
#define NT 704          // 2 threads per node slot (352 slots)

typedef unsigned long long ull;

static __device__ float g_X0[64*13*CNN];
static __device__ float g_X1[64*13*CNN];
static __device__ float g_skip[64*256*NN];

// ---- MUFU helpers (SFU pipe; rel err ~1e-6) ---------------------------------
__device__ __forceinline__ float ex2_(float x){ float r; asm("ex2.approx.f32 %0,%1;":"=f"(r):"f"(x)); return r; }
__device__ __forceinline__ float lg2_(float x){ float r; asm("lg2.approx.f32 %0,%1;":"=f"(r):"f"(x)); return r; }
__device__ __forceinline__ float rcp_(float x){ float r; asm("rcp.approx.f32 %0,%1;":"=f"(r):"f"(x)); return r; }

// ---- packed f32x2 helpers (sm_100+) -----------------------------------------
__device__ __forceinline__ ull pack2(float lo, float hi){
  ull r; asm("mov.b64 %0, {%1,%2};" : "=l"(r) : "f"(lo), "f"(hi)); return r;
}
__device__ __forceinline__ void unpack2(ull v, float& lo, float& hi){
  asm("mov.b64 {%0,%1}, %2;" : "=f"(lo), "=f"(hi) : "l"(v));
}
__device__ __forceinline__ ull fma2(ull a, ull b, ull c){
  ull d; asm("fma.rn.f32x2 %0, %1, %2, %3;" : "=l"(d) : "l"(a), "l"(b), "l"(c)); return d;
}
__device__ __forceinline__ ull mul2(ull a, ull b){
  ull d; asm("mul.rn.f32x2 %0, %1, %2;" : "=l"(d) : "l"(a), "l"(b)); return d;
}
__device__ __forceinline__ ull add2(ull a, ull b){
  ull d; asm("add.rn.f32x2 %0, %1, %2;" : "=l"(d) : "l"(a), "l"(b)); return d;
}

// ---- start conv + skip zero -------------------------------------------------
__global__ __launch_bounds__(256) void start_kernel(const float* __restrict__ x,
                                                    const float* __restrict__ sW,
                                                    const float* __restrict__ sb){
  int i = blockIdx.x*256 + threadIdx.x;
  const int tot = 64*13*CNN;
  if (i < tot){
    int n = i % NN; int r = i / NN;
    int c = r & 31; r >>= 5;
    int t = r % 13; int b = r / 13;
    float v0 = x[((b*2+0)*NN + n)*13 + t];
    float v1 = x[((b*2+1)*NN + n)*13 + t];
    g_X0[i] = fmaf(sW[c*2], v0, fmaf(sW[c*2+1], v1, sb[c]));
  } else {
    int j = i - tot;
    if (j < 64*256*NN) g_skip[j] = 0.f;
  }
}

// ---- fused layer kernel -----------------------------------------------------
#define OFF_K     7040
#define OFF_MXP   14080
#define OFF_ZP    14784
#define OFF_GX    15488    // [352][36]
#define OFF_W     28160    // staged weights (max 4192)
#define OFF_ROW   32352    // [352]
#define LAYER_SMEM_BYTES (32704*4)

__global__ __launch_bounds__(NT,1) void layer_kernel(
    int layer, int dil, int do_att, int parity,
    const float* __restrict__ fW,  const float* __restrict__ fb,
    const float* __restrict__ gW,  const float* __restrict__ gb,
    const float* __restrict__ skW, const float* __restrict__ skb,
    const float* __restrict__ qW,  const float* __restrict__ qb,
    const float* __restrict__ kW,  const float* __restrict__ kb,
    const float* __restrict__ mW,  const float* __restrict__ mb,
    const float* __restrict__ bng, const float* __restrict__ bnb,
    const float* __restrict__ bnm, const float* __restrict__ bnv,
    const float* __restrict__ emb)
{
  extern __shared__ __align__(16) float sm[];
  const float* __restrict__ Xin  = parity ? g_X1 : g_X0;
  float* __restrict__       Xout = parity ? g_X0 : g_X1;
  const int t = blockIdx.x, b = blockIdx.y, tid = threadIdx.x;
  const int Tout = gridDim.x;
  const int n = tid % 352;
  const int h = tid / 352;
  const int last_t = (t == Tout-1);

  float* s_swt = sm;               // [32][256] (phase 0..1b)
  float* s_q   = sm;               // [352][20] (phases 2-4)
  float* s_k   = sm + OFF_K;       // [352][20]
  float* s_mxp = sm + OFF_MXP;     // [2][352]
  float* s_zp  = sm + OFF_ZP;      // [2][352]
  float* s_xa  = sm;               // [352][36] (after xa loop)
  float* s_gx  = sm + OFF_GX;      // [352][36]
  float* wreg  = sm + OFF_W;
  float* s_row = sm + OFF_ROW;

  // ---- phase 0: stage gated weights [ci][kind f0,f1,g0,g1][co] + biases -----
  for (int idx = tid; idx < 4096; idx += NT){
    int ci = idx>>7, r = idx&127, kind = r>>5, co = r&31;
    const float* src = (kind < 2) ? fW : gW;
    wreg[idx] = src[((layer*32+co)*32+ci)*2 + (kind & 1)];
  }
  if (tid < 64) wreg[4096+tid] = (tid<32) ? fb[layer*32+tid] : gb[layer*32+tid-32];
  if (last_t){
    for (int idx = tid; idx < 8192; idx += NT){
      int ci = idx>>8, o = idx&255;
      s_swt[idx] = skW[(layer*256+o)*32 + ci];
    }
  }
  __syncthreads();

  // ---- phase 1: gated conv (packed f32x2), half the channels per thread -----
  const int base_in = (b*13 + t)*CNN;
  if (n < NN){
    const float* xin = Xin + base_in + n;
    const float* xrn = xin + dil*CNN;
    ull f2[8], g2[8];
    {
      const ulonglong2* fbp = (const ulonglong2*)(wreg + 4096 + 16*h);
      const ulonglong2* gbp = (const ulonglong2*)(wreg + 4128 + 16*h);
      #pragma unroll
      for (int p=0;p<4;p++){ ulonglong2 a=fbp[p], c=gbp[p]; f2[2*p]=a.x; f2[2*p+1]=a.y; g2[2*p]=c.x; g2[2*p+1]=c.y; }
    }
    #pragma unroll 4
    for (int ci=0; ci<32; ci++){
      float xl = xin[ci*NN], xr = xrn[ci*NN];
      ull xl2 = pack2(xl,xl), xr2 = pack2(xr,xr);
      const ulonglong2* p0 = (const ulonglong2*)(wreg + ci*128      + 16*h);
      const ulonglong2* p1 = (const ulonglong2*)(wreg + ci*128 + 32 + 16*h);
      const ulonglong2* p2 = (const ulonglong2*)(wreg + ci*128 + 64 + 16*h);
      const ulonglong2* p3 = (const ulonglong2*)(wreg + ci*128 + 96 + 16*h);
      #pragma unroll
      for (int p4=0;p4<4;p4++){
        ulonglong2 a=p0[p4], bb=p1[p4], c=p2[p4], d=p3[p4];
        f2[2*p4]   = fma2(xl2, a.x,  f2[2*p4]);   f2[2*p4+1] = fma2(xl2, a.y,  f2[2*p4+1]);
        f2[2*p4]   = fma2(xr2, bb.x, f2[2*p4]);   f2[2*p4+1] = fma2(xr2, bb.y, f2[2*p4+1]);
        g2[2*p4]   = fma2(xl2, c.x,  g2[2*p4]);   g2[2*p4+1] = fma2(xl2, c.y,  g2[2*p4+1]);
        g2[2*p4]   = fma2(xr2, d.x,  g2[2*p4]);   g2[2*p4+1] = fma2(xr2, d.y,  g2[2*p4+1]);
      }
    }
    #pragma unroll
    for (int p=0;p<8;p++){
      float fa,fb2, ga,gb2;
      unpack2(f2[p], fa, fb2); unpack2(g2[p], ga, gb2);
      float efa = ex2_(-2.88539008f*fa), ega = ex2_(-1.44269504f*ga);
      float efb = ex2_(-2.88539008f*fb2), egb = ex2_(-1.44269504f*gb2);
      s_gx[n*36 + 16*h + 2*p]   = (1.f - efa) * rcp_((1.f + efa)*(1.f + ega));
      s_gx[n*36 + 16*h + 2*p+1] = (1.f - efb) * rcp_((1.f + efb)*(1.f + egb));
    }
  }
  __syncthreads();

  // ---- stage attention-phase weights ----------------------------------------
  if (do_att){
    for (int idx = tid; idx < 1536; idx += NT){
      int half = (idx >= 768) ? 1 : 0;
      int r = idx - half*768; int cin = r>>4, d = r&15;
      wreg[idx] = (half ? kW : qW)[(layer*16+d)*48 + cin];
    }
    if (tid < 32) wreg[1536+tid] = (tid<16) ? qb[layer*16+tid] : kb[layer*16+tid-16];
    for (int idx = tid; idx < 2048; idx += NT){
      int c = idx>>5, o = idx&31;
      wreg[1568+idx] = mW[(layer*32+o)*64 + c];
    }
    if (tid < 32){
      wreg[3616+tid] = mb[layer*32+tid];
      float sc = bng[layer*32+tid] * rsqrtf(bnv[layer*32+tid] + 1e-5f);
      wreg[3648+tid] = sc;
      wreg[3680+tid] = bnb[layer*32+tid] - bnm[layer*32+tid]*sc;
    }
  }

  // ---- phase 1b: skip contribution (scalar; only last time index) -----------
  if (last_t && n < NN){
    float* skp = g_skip + b*256*NN + n;
    const float4* gxv = (const float4*)(s_gx + n*36);
    #pragma unroll 1
    for (int og=0; og<4; og++){
      int ot = 4*h + og;
      float acc[32];
      #pragma unroll
      for (int j=0;j<32;j++) acc[j] = skb[layer*256 + ot*32 + j];
      #pragma unroll 2
      for (int ci4=0; ci4<8; ci4++){
        float4 g4 = gxv[ci4];
        #pragma unroll
        for (int jj=0; jj<4; jj++){
          float xv = (jj==0)?g4.x:(jj==1)?g4.y:(jj==2)?g4.z:g4.w;
          const float4* wv = (const float4*)(s_swt + (ci4*4+jj)*256 + ot*32);
          #pragma unroll
          for (int j4=0;j4<8;j4++){
            float4 w = wv[j4];
            acc[4*j4+0]=fmaf(w.x,xv,acc[4*j4+0]); acc[4*j4+1]=fmaf(w.y,xv,acc[4*j4+1]);
            acc[4*j4+2]=fmaf(w.z,xv,acc[4*j4+2]); acc[4*j4+3]=fmaf(w.w,xv,acc[4*j4+3]);
          }
        }
      }
      #pragma unroll
      for (int j=0;j<32;j++) skp[(ot*32+j)*NN] += acc[j];
    }
  }
  if (!do_att) return;
  __syncthreads();

  // ---- phase 2: h=0 -> q (log2e/4 folded), h=1 -> k (packed) ----------------
  if (n < NN){
    ull a2[8];
    const float* wb = wreg + 768*h;
    {
      const ulonglong2* bp = (const ulonglong2*)(wreg + 1536 + 16*h);
      #pragma unroll
      for (int p=0;p<4;p++){ ulonglong2 v=bp[p]; a2[2*p]=v.x; a2[2*p+1]=v.y; }
    }
    const float4* gxv = (const float4*)(s_gx + n*36);
    #pragma unroll 2
    for (int ci4=0; ci4<8; ci4++){
      float4 g4 = gxv[ci4];
      #pragma unroll
      for (int jj=0; jj<4; jj++){
        float xv = (jj==0)?g4.x:(jj==1)?g4.y:(jj==2)?g4.z:g4.w;
        ull xv2 = pack2(xv,xv);
        const ulonglong2* wv = (const ulonglong2*)(wb + (ci4*4+jj)*16);
        ulonglong2 wA=wv[0], wB=wv[1], wC=wv[2], wD=wv[3];
        a2[0]=fma2(xv2,wA.x,a2[0]); a2[1]=fma2(xv2,wA.y,a2[1]);
        a2[2]=fma2(xv2,wB.x,a2[2]); a2[3]=fma2(xv2,wB.y,a2[3]);
        a2[4]=fma2(xv2,wC.x,a2[4]); a2[5]=fma2(xv2,wC.y,a2[5]);
        a2[6]=fma2(xv2,wD.x,a2[6]); a2[7]=fma2(xv2,wD.y,a2[7]);
      }
    }
    #pragma unroll 4
    for (int e=0; e<16; e++){
      float xv = emb[e*NN+n];
      ull xv2 = pack2(xv,xv);
      const ulonglong2* wv = (const ulonglong2*)(wb + (32+e)*16);
      ulonglong2 wA=wv[0], wB=wv[1], wC=wv[2], wD=wv[3];
      a2[0]=fma2(xv2,wA.x,a2[0]); a2[1]=fma2(xv2,wA.y,a2[1]);
      a2[2]=fma2(xv2,wB.x,a2[2]); a2[3]=fma2(xv2,wB.y,a2[3]);
      a2[4]=fma2(xv2,wC.x,a2[4]); a2[5]=fma2(xv2,wC.y,a2[5]);
      a2[6]=fma2(xv2,wD.x,a2[6]); a2[7]=fma2(xv2,wD.y,a2[7]);
    }
    if (h == 0){
      ull qsc2 = pack2(0.36067376f, 0.36067376f);   // log2e/4
      ull* qp = (ull*)(s_q + n*20);
      #pragma unroll
      for (int p=0;p<8;p++) qp[p] = mul2(a2[p], qsc2);
    } else {
      ull* kp = (ull*)(s_k + n*20);
      #pragma unroll
      for (int p=0;p<8;p++) kp[p] = a2[p];
    }
  }
  __syncthreads();

  const int m0 = h ? 163 : 0, m1 = h ? NN : 163;

  // ---- phase 3: online single-pass log-sum-exp (packed dot) -----------------
  if (n < NN){
    ull qq[8];
    {
      const ulonglong2* qp = (const ulonglong2*)(s_q + n*20);
      #pragma unroll
      for (int p=0;p<4;p++){ ulonglong2 v=qp[p]; qq[2*p]=v.x; qq[2*p+1]=v.y; }
    }
    float mx = -1e30f, Z = 0.f;
    #pragma unroll 2
    for (int m=m0; m<m1; m++){
      const ulonglong2* kp = (const ulonglong2*)(s_k + m*20);
      ulonglong2 kA=kp[0], kB=kp[1], kC=kp[2], kD=kp[3];
      ull d0 = mul2(qq[0],kA.x); d0=fma2(qq[1],kA.y,d0); d0=fma2(qq[2],kB.x,d0); d0=fma2(qq[3],kB.y,d0);
      ull d1 = mul2(qq[4],kC.x); d1=fma2(qq[5],kC.y,d1); d1=fma2(qq[6],kD.x,d1); d1=fma2(qq[7],kD.y,d1);
      float s0,s1,s2,s3; unpack2(d0,s0,s1); unpack2(d1,s2,s3);
      float s = (s0+s1)+(s2+s3);
      float nm = fmaxf(mx, s);
      Z = fmaf(Z, ex2_(mx - nm), ex2_(s - nm));
      mx = nm;
    }
    s_mxp[h*352+n] = mx;
    s_zp [h*352+n] = Z;
  }
  __syncthreads();
  if (h == 0 && n < NN){
    float mx0 = s_mxp[n], mx1 = s_mxp[352+n];
    float mx  = fmaxf(mx0, mx1);
    float Z   = s_zp[n]*ex2_(mx0-mx) + s_zp[352+n]*ex2_(mx1-mx);
    s_row[n]  = mx + lg2_(Z);
  }
  __syncthreads();

  // ---- phase 4: column pass (packed dot + packed accumulate) ----------------
  ull xa2[16];
  #pragma unroll
  for (int j=0;j<16;j++) xa2[j] = 0ULL;
  if (n < NN){
    ull kk[8];
    {
      const ulonglong2* kp = (const ulonglong2*)(s_k + n*20);
      #pragma unroll
      for (int p=0;p<4;p++){ ulonglong2 v=kp[p]; kk[2*p]=v.x; kk[2*p+1]=v.y; }
    }
    #pragma unroll 2
    for (int m=m0; m<m1; m++){
      const ulonglong2* qp = (const ulonglong2*)(s_q + m*20);
      ulonglong2 qA=qp[0], qB=qp[1], qC=qp[2], qD=qp[3];
      ull d0 = mul2(kk[0],qA.x); d0=fma2(kk[1],qA.y,d0); d0=fma2(kk[2],qB.x,d0); d0=fma2(kk[3],qB.y,d0);
      ull d1 = mul2(kk[4],qC.x); d1=fma2(kk[5],qC.y,d1); d1=fma2(kk[6],qD.x,d1); d1=fma2(kk[7],qD.y,d1);
      float s0,s1,s2,s3; unpack2(d0,s0,s1); unpack2(d1,s2,s3);
      float s = (s0+s1)+(s2+s3);
      float w = ex2_(s - s_row[m]);
      ull w2 = pack2(w,w);
      const ulonglong2* gv = (const ulonglong2*)(s_gx + m*36);
      #pragma unroll
      for (int j=0;j<8;j++){
        ulonglong2 g = gv[j];
        xa2[2*j]   = fma2(w2, g.x, xa2[2*j]);
        xa2[2*j+1] = fma2(w2, g.y, xa2[2*j+1]);
      }
    }
  }
  __syncthreads();
  if (h == 0 && n < NN){
    ull* xp = (ull*)(s_xa + n*36);
    #pragma unroll
    for (int j=0;j<16;j++) xp[j] = xa2[j];
  }
  __syncthreads();
  if (h == 1 && n < NN){
    ull* xp = (ull*)(s_xa + n*36);
    #pragma unroll
    for (int j=0;j<16;j++) xp[j] = add2(xp[j], xa2[j]);
  }
  __syncthreads();

  // ---- phase 5: mlp (packed) + residual + BN ---------------------------------
  if (n < NN){
    ull o2[8];
    {
      const ulonglong2* bp = (const ulonglong2*)(wreg + 3616 + 16*h);
      #pragma unroll
      for (int p=0;p<4;p++){ ulonglong2 v=bp[p]; o2[2*p]=v.x; o2[2*p+1]=v.y; }
    }
    const float4* gxv = (const float4*)(s_gx + n*36);
    const float4* xav = (const float4*)(s_xa + n*36);
    #pragma unroll 2
    for (int ci4=0; ci4<8; ci4++){
      float4 g4 = gxv[ci4];
      #pragma unroll
      for (int jj=0; jj<4; jj++){
        float xv = (jj==0)?g4.x:(jj==1)?g4.y:(jj==2)?g4.z:g4.w;
        ull xv2 = pack2(xv,xv);
        const ulonglong2* wv = (const ulonglong2*)(wreg + 1568 + (ci4*4+jj)*32 + 16*h);
        ulonglong2 wA=wv[0], wB=wv[1];
        o2[0]=fma2(xv2,wA.x,o2[0]); o2[1]=fma2(xv2,wA.y,o2[1]);
        o2[2]=fma2(xv2,wB.x,o2[2]); o2[3]=fma2(xv2,wB.y,o2[3]);
        wA=wv[2]; wB=wv[3];
        o2[4]=fma2(xv2,wA.x,o2[4]); o2[5]=fma2(xv2,wA.y,o2[5]);
        o2[6]=fma2(xv2,wB.x,o2[6]); o2[7]=fma2(xv2,wB.y,o2[7]);
      }
    }
    #pragma unroll 2
    for (int ci4=0; ci4<8; ci4++){
      float4 g4 = xav[ci4];
      #pragma unroll
      for (int jj=0; jj<4; jj++){
        float xv = (jj==0)?g4.x:(jj==1)?g4.y:(jj==2)?g4.z:g4.w;
        ull xv2 = pack2(xv,xv);
        const ulonglong2* wv = (const ulonglong2*)(wreg + 1568 + (32+ci4*4+jj)*32 + 16*h);
        ulonglong2 wA=wv[0], wB=wv[1];
        o2[0]=fma2(xv2,wA.x,o2[0]); o2[1]=fma2(xv2,wA.y,o2[1]);
        o2[2]=fma2(xv2,wB.x,o2[2]); o2[3]=fma2(xv2,wB.y,o2[3]);
        wA=wv[2]; wB=wv[3];
        o2[4]=fma2(xv2,wA.x,o2[4]); o2[5]=fma2(xv2,wA.y,o2[5]);
        o2[6]=fma2(xv2,wB.x,o2[6]); o2[7]=fma2(xv2,wB.y,o2[7]);
      }
    }
    const float* rin = Xin + base_in + dil*CNN + n;
    float* outp = Xout + base_in + n;
    #pragma unroll
    for (int p=0; p<8; p++){
      float va, vb; unpack2(o2[p], va, vb);
      int c0 = 16*h + 2*p, c1 = c0 + 1;
      float v0 = va + rin[c0*NN];
      float v1 = vb + rin[c1*NN];
      outp[c0*NN] = fmaf(v0, wreg[3648+c0], wreg[3680+c0]);
      outp[c1*NN] = fmaf(v1, wreg[3648+c1], wreg[3680+c1]);
    }
  }
}

// ---- head: relu(skip) -> relu(512) -> 12 ------------------------------------
#define H_SS 0
#define H_W1 16384
#define H_H  32832
#define H_W2 37184
#define H_B1 43328
#define HEAD_SMEM_BYTES (43840*4)

__global__ __launch_bounds__(256,1) void head_kernel(
    const float* __restrict__ w1, const float* __restrict__ b1,
    const float* __restrict__ w2, const float* __restrict__ b2,
    float* __restrict__ out)
{
  extern __shared__ __align__(16) float sm[];
  float* s_s = sm + H_SS;   // [256][64]
  float* w1s = sm + H_W1;   // [64][257]
  float* h_s = sm + H_H;    // [64][68]
  float* w2t = sm + H_W2;   // [512][12]
  float* b1s = sm + H_B1;   // [512]
  const int tid = threadIdx.x;
  const int p0 = blockIdx.x*64;

  for (int idx = tid; idx < 16384; idx += 256){
    int c = idx>>6, j = idx&63, p = p0 + j;
    int b = p/NN, nn = p - b*NN;
    s_s[idx] = fmaxf(g_skip[(b*256+c)*NN + nn], 0.f);
  }
  for (int idx = tid; idx < 6144; idx += 256){
    int o = idx/12, oo = idx - o*12;
    w2t[idx] = w2[oo*512 + o];
  }
  for (int idx = tid; idx < 512; idx += 256) b1s[idx] = b1[idx];

  const int op  = tid & 63, jg = tid >> 6;
  const int oo  = tid % 12, j0 = (tid/12)*4;
  float accO[4] = {0.f,0.f,0.f,0.f};

  for (int ot = 0; ot < 8; ot++){
    __syncthreads();
    for (int idx = tid; idx < 16384; idx += 256){
      int o = idx>>8, c = idx&255;
      w1s[o*257+c] = w1[(ot*64+o)*256 + c];
    }
    __syncthreads();
    {
      float acc[16];
      float bv = b1s[ot*64+op];
      #pragma unroll
      for (int k=0;k<16;k++) acc[k]=bv;
      #pragma unroll 2
      for (int c=0; c<256; c++){
        float w = w1s[op*257+c];
        const float4* sp = (const float4*)(s_s + c*64 + jg*16);
        #pragma unroll
        for (int k4=0;k4<4;k4++){
          float4 s4 = sp[k4];
          acc[4*k4+0]=fmaf(w,s4.x,acc[4*k4+0]); acc[4*k4+1]=fmaf(w,s4.y,acc[4*k4+1]);
          acc[4*k4+2]=fmaf(w,s4.z,acc[4*k4+2]); acc[4*k4+3]=fmaf(w,s4.w,acc[4*k4+3]);
        }
      }
      float4* hp = (float4*)(h_s + op*68 + jg*16);
      #pragma unroll
      for (int k4=0;k4<4;k4++)
        hp[k4] = make_float4(fmaxf(acc[4*k4+0],0.f), fmaxf(acc[4*k4+1],0.f),
                             fmaxf(acc[4*k4+2],0.f), fmaxf(acc[4*k4+3],0.f));
    }
    __syncthreads();
    if (tid < 192){
      #pragma unroll 4
      for (int o=0; o<64; o++){
        float w = w2t[(ot*64+o)*12 + oo];
        const float4* hp = (const float4*)(h_s + o*68 + j0);
        float4 h4 = hp[0];
        accO[0]=fmaf(w,h4.x,accO[0]); accO[1]=fmaf(w,h4.y,accO[1]);
        accO[2]=fmaf(w,h4.z,accO[2]); accO[3]=fmaf(w,h4.w,accO[3]);
      }
    }
  }
  if (tid < 192){
    float bb = b2[oo];
    #pragma unroll
    for (int k=0;k<4;k++){
      int p = p0 + j0 + k;
      int b = p/NN, nn = p - b*NN;
      out[(b*12+oo)*NN + nn] = accO[k] + bb;
    }
  }
}

// ---- host -------------------------------------------------------------------
extern "C" void kernel_launch(void* const* d_in, const int* in_sizes, int n_in,
                              void* d_out, int out_size){
  const float* x    = (const float*)d_in[0];
  const float* emb  = (const float*)d_in[1];
  const float* stW  = (const float*)d_in[2];
  const float* stb  = (const float*)d_in[3];
  const float* fW   = (const float*)d_in[4];
  const float* fb   = (const float*)d_in[5];
  const float* gW   = (const float*)d_in[6];
  const float* gb   = (const float*)d_in[7];
  const float* skW  = (const float*)d_in[8];
  const float* skb  = (const float*)d_in[9];
  const float* qW   = (const float*)d_in[10];
  const float* qb   = (const float*)d_in[11];
  const float* kW   = (const float*)d_in[12];
  const float* kb   = (const float*)d_in[13];
  const float* mW   = (const float*)d_in[14];
  const float* mb   = (const float*)d_in[15];
  const float* bng  = (const float*)d_in[16];
  const float* bnb  = (const float*)d_in[17];
  const float* bnm  = (const float*)d_in[18];
  const float* bnv  = (const float*)d_in[19];
  const float* e1W  = (const float*)d_in[20];
  const float* e1b  = (const float*)d_in[21];
  const float* e2W  = (const float*)d_in[22];
  const float* e2b  = (const float*)d_in[23];
  float* out = (float*)d_out;

  cudaFuncSetAttribute(layer_kernel, cudaFuncAttributeMaxDynamicSharedMemorySize, LAYER_SMEM_BYTES);
  cudaFuncSetAttribute(head_kernel,  cudaFuncAttributeMaxDynamicSharedMemorySize, HEAD_SMEM_BYTES);

  start_kernel<<<54600, 256>>>(x, stW, stb);

  const int dil[8]  = {1,2,1,2,1,2,1,2};
  const int Tout[8] = {12,10,9,7,6,4,3,1};
  for (int i = 0; i < 8; i++){
    layer_kernel<<<dim3(Tout[i], 64), NT, LAYER_SMEM_BYTES>>>(
        i, dil[i], (i != 7) ? 1 : 0, i & 1,
        fW, fb, gW, gb, skW, skb, qW, qb, kW, kb, mW, mb,
        bng, bnb, bnm, bnv, emb);
  }

  head_kernel<<<325, 256, HEAD_SMEM_BYTES>>>(e1W, e1b, e2W, e2b, out);
}